// round 1
// baseline (speedup 1.0000x reference)
#include <cuda_runtime.h>
#include <math.h>

#define D_MODEL 512
#define F_FF    2048
#define N_EXP   8
#define N_TOK   8192
#define N_ASSIGN (N_TOK * 2)
#define NT_TILES 160
#define BM 128
#define BN 128
#define BK 16

#define OUT_LOGITS ((size_t)N_TOK * D_MODEL)                     // 4194304
#define OUT_PROBS  (OUT_LOGITS + (size_t)N_TOK * N_EXP)          // 4259840
#define OUT_Z      (OUT_PROBS + (size_t)N_TOK * N_EXP)           // 4325376
#define OUT_LB     (OUT_Z + 1)
#define OUT_LOAD   (OUT_LB + 1)
#define OUT_CNT    (OUT_LOAD + N_EXP)

// ---------------- static scratch (no allocations allowed) ----------------
__device__ float g_hidden[(N_ASSIGN + BM) * F_FF];    // ~135 MB
__device__ float g_y[(N_ASSIGN + BM) * D_MODEL];      // ~34 MB
__device__ int   g_tok[N_ASSIGN + BM];
__device__ int   g_pos[N_ASSIGN];
__device__ int   g_topk_idx[N_ASSIGN];
__device__ float g_topk_w[N_ASSIGN];
__device__ int   g_cnt[N_EXP];
__device__ int   g_cursor[N_EXP];
__device__ float g_zsum;
__device__ float g_loadsum[N_EXP];
__device__ int   g_tile_e[NT_TILES];
__device__ int   g_tile_p0[NT_TILES];
__device__ int   g_tile_rows[NT_TILES];

__device__ __forceinline__ float gelu_f(float x) {
    const float c = 0.7978845608028654f;  // sqrt(2/pi)
    float x3 = x * x * x;
    return 0.5f * x * (1.0f + tanhf(c * (x + 0.044715f * x3)));
}

// ---------------- init ----------------
__global__ void init_kernel() {
    int t = threadIdx.x;
    if (t < N_EXP) { g_cnt[t] = 0; g_loadsum[t] = 0.0f; }
    if (t == 0) g_zsum = 0.0f;
}

// ---------------- gating: one warp per token ----------------
__global__ __launch_bounds__(256) void gating_kernel(
    const float* __restrict__ tokens, const float* __restrict__ gate_w,
    float* __restrict__ out)
{
    __shared__ float gwT[N_EXP][D_MODEL];  // transposed for conflict-free reads
    __shared__ float s_load[N_EXP];
    __shared__ int   s_cnt[N_EXP];
    __shared__ float s_z;

    int t = threadIdx.x;
    for (int i = t; i < D_MODEL * N_EXP; i += 256) {
        int d = i >> 3, e = i & 7;
        gwT[e][d] = gate_w[i];
    }
    if (t < N_EXP) { s_load[t] = 0.0f; s_cnt[t] = 0; }
    if (t == 0) s_z = 0.0f;
    __syncthreads();

    int warp = t >> 5, lane = t & 31;
    int n = blockIdx.x * 8 + warp;
    const float* x = tokens + (size_t)n * D_MODEL;

    float acc[8] = {0.f,0.f,0.f,0.f,0.f,0.f,0.f,0.f};
    for (int d = lane; d < D_MODEL; d += 32) {
        float xv = x[d];
        #pragma unroll
        for (int e = 0; e < 8; e++) acc[e] = fmaf(xv, gwT[e][d], acc[e]);
    }
    #pragma unroll
    for (int e = 0; e < 8; e++) {
        #pragma unroll
        for (int o = 16; o; o >>= 1)
            acc[e] += __shfl_down_sync(0xffffffffu, acc[e], o);
    }

    if (lane == 0) {
        float m = acc[0];
        #pragma unroll
        for (int e = 1; e < 8; e++) m = fmaxf(m, acc[e]);
        float p[8], s = 0.0f;
        #pragma unroll
        for (int e = 0; e < 8; e++) { p[e] = expf(acc[e] - m); s += p[e]; }
        float inv = 1.0f / s;
        #pragma unroll
        for (int e = 0; e < 8; e++) p[e] *= inv;

        float* gl = out + OUT_LOGITS + (size_t)n * N_EXP;
        float* pr = out + OUT_PROBS  + (size_t)n * N_EXP;
        #pragma unroll
        for (int e = 0; e < 8; e++) { gl[e] = acc[e]; pr[e] = p[e]; }

        float lse = m + logf(s);
        atomicAdd(&s_z, lse * lse);
        #pragma unroll
        for (int e = 0; e < 8; e++) atomicAdd(&s_load[e], p[e]);

        // top-2
        int i0 = 0; float m0 = p[0];
        #pragma unroll
        for (int e = 1; e < 8; e++) if (p[e] > m0) { m0 = p[e]; i0 = e; }
        int i1 = (i0 == 0) ? 1 : 0; float m1 = p[i1];
        #pragma unroll
        for (int e = 0; e < 8; e++)
            if (e != i0 && p[e] > m1) { m1 = p[e]; i1 = e; }
        float ws = m0 + m1;
        g_topk_idx[2 * n]     = i0;
        g_topk_idx[2 * n + 1] = i1;
        g_topk_w[2 * n]       = m0 / ws;
        g_topk_w[2 * n + 1]   = m1 / ws;
        atomicAdd(&s_cnt[i0], 1);
        atomicAdd(&s_cnt[i1], 1);
    }
    __syncthreads();
    if (t < N_EXP) {
        atomicAdd(&g_cnt[t], s_cnt[t]);
        atomicAdd(&g_loadsum[t], s_load[t]);
    }
    if (t == 0) atomicAdd(&g_zsum, s_z);
}

// ---------------- finalize: offsets, scalar losses, tile map ----------------
__global__ void finalize_kernel(float* __restrict__ out) {
    if (threadIdx.x != 0) return;
    int offs[N_EXP + 1];
    int off = 0;
    for (int e = 0; e < N_EXP; e++) { offs[e] = off; off += g_cnt[e]; }
    offs[N_EXP] = off;

    float lb = 0.0f;
    int tcount = 0;
    for (int e = 0; e < N_EXP; e++) {
        g_cursor[e] = offs[e];
        float load = g_loadsum[e] / (float)N_TOK;
        out[OUT_LOAD + e] = load;
        out[OUT_CNT + e]  = (float)g_cnt[e];
        lb += ((float)g_cnt[e] / (float)N_ASSIGN) * load;
        for (int r = 0; r < g_cnt[e]; r += BM) {
            g_tile_e[tcount]    = e;
            g_tile_p0[tcount]   = offs[e] + r;
            int rem = g_cnt[e] - r;
            g_tile_rows[tcount] = rem < BM ? rem : BM;
            tcount++;
        }
    }
    for (int i = tcount; i < NT_TILES; i++) g_tile_rows[i] = 0;
    out[OUT_LB] = (float)N_EXP * lb;
    out[OUT_Z]  = g_zsum / (float)N_TOK;
}

// ---------------- scatter tokens into per-expert lists ----------------
__global__ void scatter_kernel() {
    int n = blockIdx.x * blockDim.x + threadIdx.x;
    if (n >= N_TOK) return;
    #pragma unroll
    for (int k = 0; k < 2; k++) {
        int e = g_topk_idx[2 * n + k];
        int pos = atomicAdd(&g_cursor[e], 1);
        g_tok[pos] = n;
        g_pos[2 * n + k] = pos;
    }
}

// ---------------- GEMM1: hidden = gelu(gather(tokens) @ w1[e] + b1[e]) ----------------
__global__ __launch_bounds__(256, 2) void gemm1_kernel(
    const float* __restrict__ tokens, const float* __restrict__ w1,
    const float* __restrict__ b1)
{
    int tile = blockIdx.x;
    int rows = g_tile_rows[tile];
    if (rows == 0) return;
    int e  = g_tile_e[tile];
    int p0 = g_tile_p0[tile];
    int c0 = blockIdx.y * BN;

    __shared__ float As[BK][BM + 4];
    __shared__ float Bs[BK][BN];
    __shared__ int   s_tok[BM];

    int t = threadIdx.x;
    if (t < BM) {
        int r = (t < rows) ? t : 0;
        s_tok[t] = g_tok[p0 + r];
    }
    __syncthreads();

    int arow = t >> 1, aseg = (t & 1) * 8;
    int brow = t >> 4, bcol = (t & 15) * 8;
    int ty = t >> 4, tx = t & 15;

    const float* Aptr = tokens + (size_t)s_tok[arow] * D_MODEL + aseg;
    const float* Bptr = w1 + (size_t)e * D_MODEL * F_FF + (size_t)brow * F_FF + c0 + bcol;

    float acc[8][8];
    #pragma unroll
    for (int i = 0; i < 8; i++)
        #pragma unroll
        for (int j = 0; j < 8; j++) acc[i][j] = 0.0f;

    for (int k0 = 0; k0 < D_MODEL; k0 += BK) {
        float4 a0 = *(const float4*)(Aptr);
        float4 a1 = *(const float4*)(Aptr + 4);
        float4 b0 = *(const float4*)(Bptr);
        float4 b1v = *(const float4*)(Bptr + 4);
        Aptr += BK;
        Bptr += (size_t)BK * F_FF;
        __syncthreads();
        As[aseg + 0][arow] = a0.x; As[aseg + 1][arow] = a0.y;
        As[aseg + 2][arow] = a0.z; As[aseg + 3][arow] = a0.w;
        As[aseg + 4][arow] = a1.x; As[aseg + 5][arow] = a1.y;
        As[aseg + 6][arow] = a1.z; As[aseg + 7][arow] = a1.w;
        *(float4*)&Bs[brow][bcol]     = b0;
        *(float4*)&Bs[brow][bcol + 4] = b1v;
        __syncthreads();
        #pragma unroll
        for (int k = 0; k < BK; k++) {
            float4 af0 = *(const float4*)&As[k][ty * 8];
            float4 af1 = *(const float4*)&As[k][ty * 8 + 4];
            float4 bf0 = *(const float4*)&Bs[k][tx * 8];
            float4 bf1 = *(const float4*)&Bs[k][tx * 8 + 4];
            float a[8] = {af0.x, af0.y, af0.z, af0.w, af1.x, af1.y, af1.z, af1.w};
            float b[8] = {bf0.x, bf0.y, bf0.z, bf0.w, bf1.x, bf1.y, bf1.z, bf1.w};
            #pragma unroll
            for (int i = 0; i < 8; i++)
                #pragma unroll
                for (int j = 0; j < 8; j++)
                    acc[i][j] = fmaf(a[i], b[j], acc[i][j]);
        }
    }

    const float* b1p = b1 + (size_t)e * F_FF + c0 + tx * 8;
    float bias[8];
    #pragma unroll
    for (int j = 0; j < 8; j++) bias[j] = b1p[j];

    #pragma unroll
    for (int i = 0; i < 8; i++) {
        int row = ty * 8 + i;
        if (row < rows) {
            float* hp = g_hidden + (size_t)(p0 + row) * F_FF + c0 + tx * 8;
            float v[8];
            #pragma unroll
            for (int j = 0; j < 8; j++) v[j] = gelu_f(acc[i][j] + bias[j]);
            *(float4*)hp       = make_float4(v[0], v[1], v[2], v[3]);
            *(float4*)(hp + 4) = make_float4(v[4], v[5], v[6], v[7]);
        }
    }
}

// ---------------- GEMM2: y = hidden @ w2[e] + b2[e] ----------------
__global__ __launch_bounds__(256, 2) void gemm2_kernel(
    const float* __restrict__ w2, const float* __restrict__ b2)
{
    int tile = blockIdx.x;
    int rows = g_tile_rows[tile];
    if (rows == 0) return;
    int e  = g_tile_e[tile];
    int p0 = g_tile_p0[tile];
    int c0 = blockIdx.y * BN;

    __shared__ float As[BK][BM + 4];
    __shared__ float Bs[BK][BN];

    int t = threadIdx.x;
    int arow = t >> 1, aseg = (t & 1) * 8;
    int brow = t >> 4, bcol = (t & 15) * 8;
    int ty = t >> 4, tx = t & 15;

    int ar = (arow < rows) ? arow : 0;
    const float* Aptr = g_hidden + (size_t)(p0 + ar) * F_FF + aseg;
    const float* Bptr = w2 + (size_t)e * F_FF * D_MODEL + (size_t)brow * D_MODEL + c0 + bcol;

    float acc[8][8];
    #pragma unroll
    for (int i = 0; i < 8; i++)
        #pragma unroll
        for (int j = 0; j < 8; j++) acc[i][j] = 0.0f;

    for (int k0 = 0; k0 < F_FF; k0 += BK) {
        float4 a0 = *(const float4*)(Aptr);
        float4 a1 = *(const float4*)(Aptr + 4);
        float4 b0 = *(const float4*)(Bptr);
        float4 b1v = *(const float4*)(Bptr + 4);
        Aptr += BK;
        Bptr += (size_t)BK * D_MODEL;
        __syncthreads();
        As[aseg + 0][arow] = a0.x; As[aseg + 1][arow] = a0.y;
        As[aseg + 2][arow] = a0.z; As[aseg + 3][arow] = a0.w;
        As[aseg + 4][arow] = a1.x; As[aseg + 5][arow] = a1.y;
        As[aseg + 6][arow] = a1.z; As[aseg + 7][arow] = a1.w;
        *(float4*)&Bs[brow][bcol]     = b0;
        *(float4*)&Bs[brow][bcol + 4] = b1v;
        __syncthreads();
        #pragma unroll
        for (int k = 0; k < BK; k++) {
            float4 af0 = *(const float4*)&As[k][ty * 8];
            float4 af1 = *(const float4*)&As[k][ty * 8 + 4];
            float4 bf0 = *(const float4*)&Bs[k][tx * 8];
            float4 bf1 = *(const float4*)&Bs[k][tx * 8 + 4];
            float a[8] = {af0.x, af0.y, af0.z, af0.w, af1.x, af1.y, af1.z, af1.w};
            float b[8] = {bf0.x, bf0.y, bf0.z, bf0.w, bf1.x, bf1.y, bf1.z, bf1.w};
            #pragma unroll
            for (int i = 0; i < 8; i++)
                #pragma unroll
                for (int j = 0; j < 8; j++)
                    acc[i][j] = fmaf(a[i], b[j], acc[i][j]);
        }
    }

    const float* b2p = b2 + (size_t)e * D_MODEL + c0 + tx * 8;
    float bias[8];
    #pragma unroll
    for (int j = 0; j < 8; j++) bias[j] = b2p[j];

    #pragma unroll
    for (int i = 0; i < 8; i++) {
        int row = ty * 8 + i;
        if (row < rows) {
            float* yp = g_y + (size_t)(p0 + row) * D_MODEL + c0 + tx * 8;
            float v[8];
            #pragma unroll
            for (int j = 0; j < 8; j++) v[j] = acc[i][j] + bias[j];
            *(float4*)yp       = make_float4(v[0], v[1], v[2], v[3]);
            *(float4*)(yp + 4) = make_float4(v[4], v[5], v[6], v[7]);
        }
    }
}

// ---------------- combine: out[n] = w0*y[p0] + w1*y[p1] ----------------
__global__ __launch_bounds__(128) void combine_kernel(float* __restrict__ out) {
    int n = blockIdx.x;
    int pa = g_pos[2 * n], pb = g_pos[2 * n + 1];
    float w0 = g_topk_w[2 * n], w1 = g_topk_w[2 * n + 1];
    int d = threadIdx.x * 4;
    float4 y0 = *(const float4*)(g_y + (size_t)pa * D_MODEL + d);
    float4 y1 = *(const float4*)(g_y + (size_t)pb * D_MODEL + d);
    float4 r;
    r.x = w0 * y0.x + w1 * y1.x;
    r.y = w0 * y0.y + w1 * y1.y;
    r.z = w0 * y0.z + w1 * y1.z;
    r.w = w0 * y0.w + w1 * y1.w;
    *(float4*)(out + (size_t)n * D_MODEL + d) = r;
}

// ---------------- launch ----------------
extern "C" void kernel_launch(void* const* d_in, const int* in_sizes, int n_in,
                              void* d_out, int out_size) {
    const float* h_t    = (const float*)d_in[0];
    const float* gate_w = (const float*)d_in[1];
    const float* w1     = (const float*)d_in[2];
    const float* b1     = (const float*)d_in[3];
    const float* w2     = (const float*)d_in[4];
    const float* b2     = (const float*)d_in[5];
    float* out = (float*)d_out;

    init_kernel<<<1, 32>>>();
    gating_kernel<<<N_TOK / 8, 256>>>(h_t, gate_w, out);
    finalize_kernel<<<1, 32>>>(out);
    scatter_kernel<<<N_TOK / 256, 256>>>();
    gemm1_kernel<<<dim3(NT_TILES, F_FF / BN), 256>>>(h_t, w1, b1);
    gemm2_kernel<<<dim3(NT_TILES, D_MODEL / BN), 256>>>(w2, b2);
    combine_kernel<<<N_TOK, 128>>>(out);
}

// round 4
// speedup vs baseline: 1.6303x; 1.6303x over previous
#include <cuda_runtime.h>
#include <cuda_bf16.h>
#include <math.h>
#include <stdint.h>

#define D_MODEL 512
#define F_FF    2048
#define N_EXP   8
#define N_TOK   8192
#define N_ASSIGN (N_TOK * 2)
#define NT_TILES 160
#define BM 128
#define BN 128
#define BK 32
#define LDA 40          // padded row length (elems) -> 80B stride, ldmatrix conflict-free

#define OUT_LOGITS ((size_t)N_TOK * D_MODEL)
#define OUT_PROBS  (OUT_LOGITS + (size_t)N_TOK * N_EXP)
#define OUT_Z      (OUT_PROBS + (size_t)N_TOK * N_EXP)
#define OUT_LB     (OUT_Z + 1)
#define OUT_LOAD   (OUT_LB + 1)
#define OUT_CNT    (OUT_LOAD + N_EXP)

// ---------------- static scratch ----------------
__device__ __nv_bfloat16 g_tok_hi[N_TOK * D_MODEL];
__device__ __nv_bfloat16 g_tok_lo[N_TOK * D_MODEL];
__device__ __nv_bfloat16 g_w1T_hi[N_EXP * F_FF * D_MODEL];   // [E, F, D] K-major
__device__ __nv_bfloat16 g_w1T_lo[N_EXP * F_FF * D_MODEL];
__device__ __nv_bfloat16 g_w2T_hi[N_EXP * D_MODEL * F_FF];   // [E, D, F] K-major
__device__ __nv_bfloat16 g_w2T_lo[N_EXP * D_MODEL * F_FF];
__device__ __nv_bfloat16 g_hid_hi[(N_ASSIGN + BM) * F_FF];
__device__ __nv_bfloat16 g_hid_lo[(N_ASSIGN + BM) * F_FF];
__device__ float g_y[(size_t)(N_ASSIGN + BM) * D_MODEL];
__device__ int   g_tok[N_ASSIGN + BM];
__device__ int   g_pos[N_ASSIGN];
__device__ int   g_topk_idx[N_ASSIGN];
__device__ float g_topk_w[N_ASSIGN];
__device__ int   g_cnt[N_EXP];
__device__ int   g_cursor[N_EXP];
__device__ float g_zsum;
__device__ float g_loadsum[N_EXP];
__device__ int   g_tile_e[NT_TILES];
__device__ int   g_tile_p0[NT_TILES];
__device__ int   g_tile_rows[NT_TILES];

// ---------------- PTX helpers (baseline ISA only) ----------------
__device__ __forceinline__ uint32_t smem_u32(const void* p) {
    uint32_t a;
    asm("{ .reg .u64 t; cvta.to.shared.u64 t, %1; cvt.u32.u64 %0, t; }" : "=r"(a) : "l"(p));
    return a;
}
#define CP_ASYNC16(dst, src) \
    asm volatile("cp.async.cg.shared.global [%0], [%1], 16;" :: "r"(dst), "l"(src) : "memory")
#define CP_COMMIT() asm volatile("cp.async.commit_group;" ::: "memory")
#define CP_WAIT1()  asm volatile("cp.async.wait_group 1;" ::: "memory")
#define CP_WAIT0()  asm volatile("cp.async.wait_group 0;" ::: "memory")

__device__ __forceinline__ void ldsm_x4(uint32_t addr, uint32_t& r0, uint32_t& r1,
                                        uint32_t& r2, uint32_t& r3) {
    asm volatile("ldmatrix.sync.aligned.m8n8.x4.shared.b16 {%0,%1,%2,%3}, [%4];"
        : "=r"(r0), "=r"(r1), "=r"(r2), "=r"(r3) : "r"(addr));
}
__device__ __forceinline__ void mma_bf16(float* d, const uint32_t* a,
                                         uint32_t b0, uint32_t b1) {
    asm volatile(
        "mma.sync.aligned.m16n8k16.row.col.f32.bf16.bf16.f32 "
        "{%0,%1,%2,%3}, {%4,%5,%6,%7}, {%8,%9}, {%0,%1,%2,%3};"
        : "+f"(d[0]), "+f"(d[1]), "+f"(d[2]), "+f"(d[3])
        : "r"(a[0]), "r"(a[1]), "r"(a[2]), "r"(a[3]), "r"(b0), "r"(b1));
}
__device__ __forceinline__ float gelu_f(float x) {
    const float c = 0.7978845608028654f;
    float x3 = x * x * x;
    return 0.5f * x * (1.0f + tanhf(c * (x + 0.044715f * x3)));
}

// ---------------- init ----------------
__global__ void init_kernel() {
    int t = threadIdx.x;
    if (t < N_EXP) { g_cnt[t] = 0; g_loadsum[t] = 0.0f; }
    if (t == 0) g_zsum = 0.0f;
}

// ---------------- gating ----------------
__global__ __launch_bounds__(256) void gating_kernel(
    const float* __restrict__ tokens, const float* __restrict__ gate_w,
    float* __restrict__ out)
{
    __shared__ float gwT[N_EXP][D_MODEL];
    __shared__ float s_load[N_EXP];
    __shared__ int   s_cnt[N_EXP];
    __shared__ float s_z;

    int t = threadIdx.x;
    for (int i = t; i < D_MODEL * N_EXP; i += 256) {
        int d = i >> 3, e = i & 7;
        gwT[e][d] = gate_w[i];
    }
    if (t < N_EXP) { s_load[t] = 0.0f; s_cnt[t] = 0; }
    if (t == 0) s_z = 0.0f;
    __syncthreads();

    int warp = t >> 5, lane = t & 31;
    int n = blockIdx.x * 8 + warp;
    const float* x = tokens + (size_t)n * D_MODEL;

    float acc[8] = {0.f,0.f,0.f,0.f,0.f,0.f,0.f,0.f};
    for (int d = lane; d < D_MODEL; d += 32) {
        float xv = x[d];
        #pragma unroll
        for (int e = 0; e < 8; e++) acc[e] = fmaf(xv, gwT[e][d], acc[e]);
    }
    #pragma unroll
    for (int e = 0; e < 8; e++) {
        #pragma unroll
        for (int o = 16; o; o >>= 1)
            acc[e] += __shfl_down_sync(0xffffffffu, acc[e], o);
    }

    if (lane == 0) {
        float m = acc[0];
        #pragma unroll
        for (int e = 1; e < 8; e++) m = fmaxf(m, acc[e]);
        float p[8], s = 0.0f;
        #pragma unroll
        for (int e = 0; e < 8; e++) { p[e] = expf(acc[e] - m); s += p[e]; }
        float inv = 1.0f / s;
        #pragma unroll
        for (int e = 0; e < 8; e++) p[e] *= inv;

        float* gl = out + OUT_LOGITS + (size_t)n * N_EXP;
        float* pr = out + OUT_PROBS  + (size_t)n * N_EXP;
        #pragma unroll
        for (int e = 0; e < 8; e++) { gl[e] = acc[e]; pr[e] = p[e]; }

        float lse = m + logf(s);
        atomicAdd(&s_z, lse * lse);
        #pragma unroll
        for (int e = 0; e < 8; e++) atomicAdd(&s_load[e], p[e]);

        int i0 = 0; float m0 = p[0];
        #pragma unroll
        for (int e = 1; e < 8; e++) if (p[e] > m0) { m0 = p[e]; i0 = e; }
        int i1 = (i0 == 0) ? 1 : 0; float m1 = p[i1];
        #pragma unroll
        for (int e = 0; e < 8; e++)
            if (e != i0 && p[e] > m1) { m1 = p[e]; i1 = e; }
        float ws = m0 + m1;
        g_topk_idx[2 * n]     = i0;
        g_topk_idx[2 * n + 1] = i1;
        g_topk_w[2 * n]       = m0 / ws;
        g_topk_w[2 * n + 1]   = m1 / ws;
        atomicAdd(&s_cnt[i0], 1);
        atomicAdd(&s_cnt[i1], 1);
    }
    __syncthreads();
    if (t < N_EXP) {
        atomicAdd(&g_cnt[t], s_cnt[t]);
        atomicAdd(&g_loadsum[t], s_load[t]);
    }
    if (t == 0) atomicAdd(&g_zsum, s_z);
}

// ---------------- finalize ----------------
__global__ void finalize_kernel(float* __restrict__ out) {
    if (threadIdx.x != 0) return;
    int offs[N_EXP + 1];
    int off = 0;
    for (int e = 0; e < N_EXP; e++) { offs[e] = off; off += g_cnt[e]; }
    offs[N_EXP] = off;

    float lb = 0.0f;
    int tcount = 0;
    for (int e = 0; e < N_EXP; e++) {
        g_cursor[e] = offs[e];
        float load = g_loadsum[e] / (float)N_TOK;
        out[OUT_LOAD + e] = load;
        out[OUT_CNT + e]  = (float)g_cnt[e];
        lb += ((float)g_cnt[e] / (float)N_ASSIGN) * load;
        for (int r = 0; r < g_cnt[e]; r += BM) {
            g_tile_e[tcount]    = e;
            g_tile_p0[tcount]   = offs[e] + r;
            int rem = g_cnt[e] - r;
            g_tile_rows[tcount] = rem < BM ? rem : BM;
            tcount++;
        }
    }
    for (int i = tcount; i < NT_TILES; i++) g_tile_rows[i] = 0;
    out[OUT_LB] = (float)N_EXP * lb;
    out[OUT_Z]  = g_zsum / (float)N_TOK;
}

// ---------------- scatter ----------------
__global__ void scatter_kernel() {
    int n = blockIdx.x * blockDim.x + threadIdx.x;
    if (n >= N_TOK) return;
    #pragma unroll
    for (int k = 0; k < 2; k++) {
        int e = g_topk_idx[2 * n + k];
        int pos = atomicAdd(&g_cursor[e], 1);
        g_tok[pos] = n;
        g_pos[2 * n + k] = pos;
    }
}

// ---------------- token bf16 hi/lo split ----------------
__global__ __launch_bounds__(256) void convert_tokens_kernel(const float* __restrict__ h_t) {
    int i = blockIdx.x * 256 + threadIdx.x;
    float4 v = ((const float4*)h_t)[i];
    __nv_bfloat16 h0 = __float2bfloat16(v.x), h1 = __float2bfloat16(v.y);
    __nv_bfloat16 h2 = __float2bfloat16(v.z), h3 = __float2bfloat16(v.w);
    __nv_bfloat16 l0 = __float2bfloat16(v.x - __bfloat162float(h0));
    __nv_bfloat16 l1 = __float2bfloat16(v.y - __bfloat162float(h1));
    __nv_bfloat16 l2 = __float2bfloat16(v.z - __bfloat162float(h2));
    __nv_bfloat16 l3 = __float2bfloat16(v.w - __bfloat162float(h3));
    __nv_bfloat162 ph0, ph1, pl0, pl1;
    ph0.x = h0; ph0.y = h1; ph1.x = h2; ph1.y = h3;
    pl0.x = l0; pl0.y = l1; pl1.x = l2; pl1.y = l3;
    ((__nv_bfloat162*)g_tok_hi)[2*i]   = ph0;
    ((__nv_bfloat162*)g_tok_hi)[2*i+1] = ph1;
    ((__nv_bfloat162*)g_tok_lo)[2*i]   = pl0;
    ((__nv_bfloat162*)g_tok_lo)[2*i+1] = pl1;
}

// ---------------- transpose + split (device-side global targets) ----------------
// NOTE: destination arrays are referenced from DEVICE code — passing __device__
// globals as kernel args from host passes the host shadow address (ATS makes it
// silently "work" on GB300, writing host memory). That was the Round-3 bug.
__device__ __forceinline__ void transpose_split_body(
    const float* __restrict__ in, __nv_bfloat16* __restrict__ out_hi,
    __nv_bfloat16* __restrict__ out_lo, int R, int C)
{
    __shared__ float tile[32][33];
    int e = blockIdx.z;
    const float* src = in + (size_t)e * R * C;
    int c0 = blockIdx.x * 32, r0 = blockIdx.y * 32;
    int tx = threadIdx.x, ty = threadIdx.y;
    #pragma unroll
    for (int i = ty; i < 32; i += 8)
        tile[i][tx] = src[(size_t)(r0 + i) * C + c0 + tx];
    __syncthreads();
    __nv_bfloat16* dh = out_hi + (size_t)e * R * C;
    __nv_bfloat16* dl = out_lo + (size_t)e * R * C;
    #pragma unroll
    for (int i = ty; i < 32; i += 8) {
        float v = tile[tx][i];
        __nv_bfloat16 h = __float2bfloat16(v);
        __nv_bfloat16 l = __float2bfloat16(v - __bfloat162float(h));
        dh[(size_t)(c0 + i) * R + r0 + tx] = h;
        dl[(size_t)(c0 + i) * R + r0 + tx] = l;
    }
}
__global__ __launch_bounds__(256) void transpose_split_w1(const float* __restrict__ in) {
    transpose_split_body(in, g_w1T_hi, g_w1T_lo, D_MODEL, F_FF);
}
__global__ __launch_bounds__(256) void transpose_split_w2(const float* __restrict__ in) {
    transpose_split_body(in, g_w2T_hi, g_w2T_lo, F_FF, D_MODEL);
}

// =============== warp-MMA GEMM kernels (bf16 HMMA, 3-term split) ===============
struct SmemGemm {
    __nv_bfloat16 A[2][BM * LDA];
    __nv_bfloat16 B[2][BN * LDA];
    int   tok[BM];
    float bias[BN];
};

// GEMM1: hidden = gelu(gather(tokens) @ w1T^T + b1) -> split bf16 hi/lo
__global__ __launch_bounds__(256) void gemm1_mma(const float* __restrict__ b1) {
    int tile = blockIdx.x;
    int rows = g_tile_rows[tile];
    if (rows == 0) return;
    int e = g_tile_e[tile], p0 = g_tile_p0[tile];
    int c0 = blockIdx.y * BN;

    __shared__ __align__(128) SmemGemm sm;
    int t = threadIdx.x, wid = t >> 5, lane = t & 31;

    if (t < BM) {
        int rr = (t < rows) ? t : (rows - 1);
        sm.tok[t]  = g_tok[p0 + rr];
        sm.bias[t] = b1[(size_t)e * F_FF + c0 + t];
    }
    __syncthreads();

    uint32_t sAb[2] = {smem_u32(sm.A[0]), smem_u32(sm.A[1])};
    uint32_t sBb[2] = {smem_u32(sm.B[0]), smem_u32(sm.B[1])};

    auto loadStage = [&](int kt, int stage) {
        int seg = kt >> 4, kk = (kt & 15) * BK;
        const __nv_bfloat16* Ag = (seg < 2) ? g_tok_hi : g_tok_lo;
        const __nv_bfloat16* Bg = (seg == 1) ? g_w1T_lo : g_w1T_hi;
        const __nv_bfloat16* Bbase = Bg + ((size_t)e * F_FF + c0) * D_MODEL + kk;
        #pragma unroll
        for (int it = 0; it < 2; it++) {
            int chunk = t + it * 256;
            int row = chunk >> 2, c = chunk & 3;
            CP_ASYNC16(sAb[stage] + row * (LDA*2) + c * 16,
                       Ag + (size_t)sm.tok[row] * D_MODEL + kk + c * 8);
        }
        #pragma unroll
        for (int it = 0; it < 2; it++) {
            int chunk = t + it * 256;
            int row = chunk >> 2, c = chunk & 3;
            CP_ASYNC16(sBb[stage] + row * (LDA*2) + c * 16,
                       Bbase + (size_t)row * D_MODEL + c * 8);
        }
        CP_COMMIT();
    };

    int wm = (wid >> 2) * 64, wn = (wid & 3) * 32;
    int laneRow = lane & 15;
    int laneK   = (lane >> 4) * 8;
    uint32_t aOff = (uint32_t)((wm + laneRow) * (LDA*2) + laneK * 2);
    uint32_t bOff = (uint32_t)((wn + laneRow) * (LDA*2) + laneK * 2);

    float acc[4][4][4];
    #pragma unroll
    for (int i = 0; i < 4; i++)
        #pragma unroll
        for (int j = 0; j < 4; j++)
            #pragma unroll
            for (int r = 0; r < 4; r++) acc[i][j][r] = 0.0f;

    const int KT = 48;
    loadStage(0, 0);
    loadStage(1, 1);
    #pragma unroll 1
    for (int kt = 0; kt < KT; kt++) {
        if (kt + 1 < KT) { CP_WAIT1(); } else { CP_WAIT0(); }
        __syncthreads();
        int st = kt & 1;
        uint32_t aB = sAb[st] + aOff, bB = sBb[st] + bOff;
        #pragma unroll
        for (int k16 = 0; k16 < 2; k16++) {
            uint32_t a[4][4], b[2][4];
            #pragma unroll
            for (int mt = 0; mt < 4; mt++)
                ldsm_x4(aB + mt * 16 * (LDA*2) + k16 * 32,
                        a[mt][0], a[mt][1], a[mt][2], a[mt][3]);
            #pragma unroll
            for (int p = 0; p < 2; p++)
                ldsm_x4(bB + p * 16 * (LDA*2) + k16 * 32,
                        b[p][0], b[p][1], b[p][2], b[p][3]);
            #pragma unroll
            for (int mt = 0; mt < 4; mt++)
                #pragma unroll
                for (int nt = 0; nt < 4; nt++)
                    mma_bf16(acc[mt][nt], a[mt], b[nt >> 1][nt & 1], b[nt >> 1][(nt & 1) + 2]);
        }
        __syncthreads();
        if (kt + 2 < KT) loadStage(kt + 2, st);
    }

    int qrow = lane >> 2, qcol = (lane & 3) * 2;
    #pragma unroll
    for (int mt = 0; mt < 4; mt++) {
        #pragma unroll
        for (int half = 0; half < 2; half++) {
            int m = wm + mt * 16 + qrow + 8 * half;
            if (m >= rows) continue;
            size_t orow = (size_t)(p0 + m) * F_FF + c0;
            #pragma unroll
            for (int nt = 0; nt < 4; nt++) {
                int nl = wn + nt * 8 + qcol;
                float v0 = gelu_f(acc[mt][nt][2 * half]     + sm.bias[nl]);
                float v1 = gelu_f(acc[mt][nt][2 * half + 1] + sm.bias[nl + 1]);
                __nv_bfloat16 h0 = __float2bfloat16(v0), h1 = __float2bfloat16(v1);
                __nv_bfloat16 l0 = __float2bfloat16(v0 - __bfloat162float(h0));
                __nv_bfloat16 l1 = __float2bfloat16(v1 - __bfloat162float(h1));
                __nv_bfloat162 ph, pl;
                ph.x = h0; ph.y = h1; pl.x = l0; pl.y = l1;
                *(__nv_bfloat162*)(g_hid_hi + orow + nl) = ph;
                *(__nv_bfloat162*)(g_hid_lo + orow + nl) = pl;
            }
        }
    }
}

// GEMM2: y = hidden @ w2T^T + b2 (fp32 out)
__global__ __launch_bounds__(256) void gemm2_mma(const float* __restrict__ b2) {
    int tile = blockIdx.x;
    int rows = g_tile_rows[tile];
    if (rows == 0) return;
    int e = g_tile_e[tile], p0 = g_tile_p0[tile];
    int c0 = blockIdx.y * BN;

    __shared__ __align__(128) SmemGemm sm;
    int t = threadIdx.x, wid = t >> 5, lane = t & 31;

    if (t < BN) sm.bias[t] = b2[(size_t)e * D_MODEL + c0 + t];
    __syncthreads();

    uint32_t sAb[2] = {smem_u32(sm.A[0]), smem_u32(sm.A[1])};
    uint32_t sBb[2] = {smem_u32(sm.B[0]), smem_u32(sm.B[1])};

    auto loadStage = [&](int kt, int stage) {
        int seg = kt >> 6, kk = (kt & 63) * BK;
        const __nv_bfloat16* Ag = (seg < 2) ? g_hid_hi : g_hid_lo;
        const __nv_bfloat16* Bg = (seg == 1) ? g_w2T_lo : g_w2T_hi;
        const __nv_bfloat16* Abase = Ag + (size_t)p0 * F_FF + kk;
        const __nv_bfloat16* Bbase = Bg + ((size_t)e * D_MODEL + c0) * F_FF + kk;
        #pragma unroll
        for (int it = 0; it < 2; it++) {
            int chunk = t + it * 256;
            int row = chunk >> 2, c = chunk & 3;
            CP_ASYNC16(sAb[stage] + row * (LDA*2) + c * 16,
                       Abase + (size_t)row * F_FF + c * 8);
        }
        #pragma unroll
        for (int it = 0; it < 2; it++) {
            int chunk = t + it * 256;
            int row = chunk >> 2, c = chunk & 3;
            CP_ASYNC16(sBb[stage] + row * (LDA*2) + c * 16,
                       Bbase + (size_t)row * F_FF + c * 8);
        }
        CP_COMMIT();
    };

    int wm = (wid >> 2) * 64, wn = (wid & 3) * 32;
    int laneRow = lane & 15;
    int laneK   = (lane >> 4) * 8;
    uint32_t aOff = (uint32_t)((wm + laneRow) * (LDA*2) + laneK * 2);
    uint32_t bOff = (uint32_t)((wn + laneRow) * (LDA*2) + laneK * 2);

    float acc[4][4][4];
    #pragma unroll
    for (int i = 0; i < 4; i++)
        #pragma unroll
        for (int j = 0; j < 4; j++)
            #pragma unroll
            for (int r = 0; r < 4; r++) acc[i][j][r] = 0.0f;

    const int KT = 192;
    loadStage(0, 0);
    loadStage(1, 1);
    #pragma unroll 1
    for (int kt = 0; kt < KT; kt++) {
        if (kt + 1 < KT) { CP_WAIT1(); } else { CP_WAIT0(); }
        __syncthreads();
        int st = kt & 1;
        uint32_t aB = sAb[st] + aOff, bB = sBb[st] + bOff;
        #pragma unroll
        for (int k16 = 0; k16 < 2; k16++) {
            uint32_t a[4][4], b[2][4];
            #pragma unroll
            for (int mt = 0; mt < 4; mt++)
                ldsm_x4(aB + mt * 16 * (LDA*2) + k16 * 32,
                        a[mt][0], a[mt][1], a[mt][2], a[mt][3]);
            #pragma unroll
            for (int p = 0; p < 2; p++)
                ldsm_x4(bB + p * 16 * (LDA*2) + k16 * 32,
                        b[p][0], b[p][1], b[p][2], b[p][3]);
            #pragma unroll
            for (int mt = 0; mt < 4; mt++)
                #pragma unroll
                for (int nt = 0; nt < 4; nt++)
                    mma_bf16(acc[mt][nt], a[mt], b[nt >> 1][nt & 1], b[nt >> 1][(nt & 1) + 2]);
        }
        __syncthreads();
        if (kt + 2 < KT) loadStage(kt + 2, st);
    }

    int qrow = lane >> 2, qcol = (lane & 3) * 2;
    #pragma unroll
    for (int mt = 0; mt < 4; mt++) {
        #pragma unroll
        for (int half = 0; half < 2; half++) {
            int m = wm + mt * 16 + qrow + 8 * half;
            if (m >= rows) continue;
            size_t orow = (size_t)(p0 + m) * D_MODEL + c0;
            #pragma unroll
            for (int nt = 0; nt < 4; nt++) {
                int nl = wn + nt * 8 + qcol;
                float2 v;
                v.x = acc[mt][nt][2 * half]     + sm.bias[nl];
                v.y = acc[mt][nt][2 * half + 1] + sm.bias[nl + 1];
                *(float2*)(g_y + orow + nl) = v;
            }
        }
    }
}

// ---------------- combine ----------------
__global__ __launch_bounds__(128) void combine_kernel(float* __restrict__ out) {
    int n = blockIdx.x;
    int pa = g_pos[2 * n], pb = g_pos[2 * n + 1];
    float w0 = g_topk_w[2 * n], w1 = g_topk_w[2 * n + 1];
    int d = threadIdx.x * 4;
    float4 y0 = *(const float4*)(g_y + (size_t)pa * D_MODEL + d);
    float4 y1 = *(const float4*)(g_y + (size_t)pb * D_MODEL + d);
    float4 r;
    r.x = w0 * y0.x + w1 * y1.x;
    r.y = w0 * y0.y + w1 * y1.y;
    r.z = w0 * y0.z + w1 * y1.z;
    r.w = w0 * y0.w + w1 * y1.w;
    *(float4*)(out + (size_t)n * D_MODEL + d) = r;
}

// ---------------- launch ----------------
extern "C" void kernel_launch(void* const* d_in, const int* in_sizes, int n_in,
                              void* d_out, int out_size) {
    const float* h_t    = (const float*)d_in[0];
    const float* gate_w = (const float*)d_in[1];
    const float* w1     = (const float*)d_in[2];
    const float* b1     = (const float*)d_in[3];
    const float* w2     = (const float*)d_in[4];
    const float* b2     = (const float*)d_in[5];
    float* out = (float*)d_out;

    init_kernel<<<1, 32>>>();
    convert_tokens_kernel<<<(N_TOK * D_MODEL / 4) / 256, 256>>>(h_t);
    transpose_split_w1<<<dim3(F_FF / 32, D_MODEL / 32, N_EXP), dim3(32, 8)>>>(w1);
    transpose_split_w2<<<dim3(D_MODEL / 32, F_FF / 32, N_EXP), dim3(32, 8)>>>(w2);
    gating_kernel<<<N_TOK / 8, 256>>>(h_t, gate_w, out);
    finalize_kernel<<<1, 32>>>(out);
    scatter_kernel<<<N_TOK / 256, 256>>>();
    gemm1_mma<<<dim3(NT_TILES, F_FF / BN), 256>>>(b1);
    gemm2_mma<<<dim3(NT_TILES, D_MODEL / BN), 256>>>(b2);
    combine_kernel<<<N_TOK, 128>>>(out);
}